// round 2
// baseline (speedup 1.0000x reference)
#include <cuda_runtime.h>

#define DM     2048
#define NHEADS 16
#define DH     128
#define BATCH  2
#define SEQ    2048
#define MTOT   (BATCH*SEQ)   // 4096

// Scratch (allocation-free): 4 x 33.5 MB
__device__ float g_q  [(size_t)MTOT * DM];
__device__ float g_k  [(size_t)MTOT * DM];
__device__ float g_v  [(size_t)MTOT * DM];
__device__ float g_att[(size_t)MTOT * DM];

// ---------------------------------------------------------------------------
// SGEMM: Y[M,N] = X[M,K] @ W[N,K]^T + bias   (torch Linear semantics)
// 128x128 block, BK=8, 256 threads, 8x8 micro-tile, padded smem (conflict-free)
// ---------------------------------------------------------------------------
__global__ __launch_bounds__(256) void sgemm_bias_kernel(
    const float* __restrict__ X, const float* __restrict__ W,
    const float* __restrict__ bias, float* __restrict__ Y,
    int Kdim, int Ndim)
{
    __shared__ float As[8][132];
    __shared__ float Bs[8][132];
    const int tid = threadIdx.x;
    const int m0 = blockIdx.y * 128;
    const int n0 = blockIdx.x * 128;
    const int tx = tid & 15;
    const int ty = tid >> 4;
    const int lrow = tid >> 1;
    const int lcol = (tid & 1) * 4;

    const float* Xp = X + (size_t)(m0 + lrow) * Kdim + lcol;
    const float* Wp = W + (size_t)(n0 + lrow) * Kdim + lcol;

    float acc[8][8];
#pragma unroll
    for (int i = 0; i < 8; i++)
#pragma unroll
        for (int j = 0; j < 8; j++) acc[i][j] = 0.f;

    for (int k0 = 0; k0 < Kdim; k0 += 8) {
        float4 xa = *(const float4*)(Xp + k0);
        float4 wa = *(const float4*)(Wp + k0);
        As[lcol+0][lrow] = xa.x; As[lcol+1][lrow] = xa.y;
        As[lcol+2][lrow] = xa.z; As[lcol+3][lrow] = xa.w;
        Bs[lcol+0][lrow] = wa.x; Bs[lcol+1][lrow] = wa.y;
        Bs[lcol+2][lrow] = wa.z; Bs[lcol+3][lrow] = wa.w;
        __syncthreads();
#pragma unroll
        for (int kk = 0; kk < 8; kk++) {
            float4 a0 = *(const float4*)&As[kk][ty*8];
            float4 a1 = *(const float4*)&As[kk][ty*8+4];
            float4 b0 = *(const float4*)&Bs[kk][tx*8];
            float4 b1 = *(const float4*)&Bs[kk][tx*8+4];
            float a[8] = {a0.x,a0.y,a0.z,a0.w,a1.x,a1.y,a1.z,a1.w};
            float b[8] = {b0.x,b0.y,b0.z,b0.w,b1.x,b1.y,b1.z,b1.w};
#pragma unroll
            for (int i = 0; i < 8; i++)
#pragma unroll
                for (int j = 0; j < 8; j++) acc[i][j] += a[i]*b[j];
        }
        __syncthreads();
    }
#pragma unroll
    for (int i = 0; i < 8; i++) {
        int row = m0 + ty*8 + i;
        float* yp = Y + (size_t)row * Ndim + n0 + tx*8;
        const float* bp = bias + n0 + tx*8;
        float4 o0 = make_float4(acc[i][0]+bp[0], acc[i][1]+bp[1],
                                acc[i][2]+bp[2], acc[i][3]+bp[3]);
        float4 o1 = make_float4(acc[i][4]+bp[4], acc[i][5]+bp[5],
                                acc[i][6]+bp[6], acc[i][7]+bp[7]);
        *(float4*)yp       = o0;
        *(float4*)(yp + 4) = o1;
    }
}

// ---------------------------------------------------------------------------
// RoPE in-place on Q and K, (B,T,H*DH) layout. 1024 threads = 16 heads x 64 pairs
// ---------------------------------------------------------------------------
__global__ void rope_kernel(float* __restrict__ q, float* __restrict__ k,
                            const float* __restrict__ sinT,
                            const float* __restrict__ cosT)
{
    int bt  = blockIdx.x;          // b*SEQ + t
    int t   = bt & (SEQ - 1);
    int tid = threadIdx.x;
    int h = tid >> 6, d = tid & 63;
    float s = sinT[t*64 + d];
    float c = cosT[t*64 + d];
    size_t base = (size_t)bt * DM + h*DH + d;
    float q1 = q[base], q2 = q[base + 64];
    q[base]      = q1*c - q2*s;
    q[base + 64] = q1*s + q2*c;
    float k1 = k[base], k2 = k[base + 64];
    k[base]      = k1*c - k2*s;
    k[base + 64] = k1*s + k2*c;
}

// ---------------------------------------------------------------------------
// Flash attention (causal), fp32. BM=128 q-rows, BN=64 kv-rows, 256 threads.
// S phase: 16x16 thread grid, 8 rows x 4 cols each. PV phase: 8 rows x 8 cols.
// Softmax state (m,l,alpha) held redundantly in registers per 16-lane row group.
// ---------------------------------------------------------------------------
#define QS_OFF 0
#define KS_OFF (128*132)
#define VS_OFF (KS_OFF + 64*132)
#define PS_OFF (VS_OFF + 64*132)
#define SMEM_FLOATS (PS_OFF + 128*68)   // 42496 floats = 169984 bytes

__global__ __launch_bounds__(256) void flash_attn_kernel(
    const float* __restrict__ Q, const float* __restrict__ K,
    const float* __restrict__ V, float* __restrict__ O)
{
    extern __shared__ float sm[];
    const int tid = threadIdx.x;
    const int i0 = blockIdx.x * 128;
    const int h  = blockIdx.y;
    const int b  = blockIdx.z;
    const int tx = tid & 15;
    const int ty = tid >> 4;
    const int r0 = ty * 8;
    const int cS = tx * 4;
    const int cO = tx * 8;
    const float scale = 0.08838834764831845f;  // 1/sqrt(128)

    const float* Qg = Q + ((size_t)(b*SEQ + i0)) * DM + h*DH;
    for (int i = tid; i < 128*32; i += 256) {
        int r = i >> 5, c = (i & 31) << 2;
        float4 v = *(const float4*)(Qg + (size_t)r*DM + c);
        v.x *= scale; v.y *= scale; v.z *= scale; v.w *= scale;
        *(float4*)&sm[QS_OFF + r*132 + c] = v;
    }

    float m_r[8], l_r[8], o[8][8];
#pragma unroll
    for (int i = 0; i < 8; i++) {
        m_r[i] = -1e30f; l_r[i] = 0.f;
#pragma unroll
        for (int j = 0; j < 8; j++) o[i][j] = 0.f;
    }

    const int ntiles = (i0 >> 6) + 2;
    for (int jt = 0; jt < ntiles; jt++) {
        const int j0 = jt * 64;
        __syncthreads();   // prev PV done with Ks/Vs/Ps; Q tile visible on iter 0
        const float* Kg = K + ((size_t)(b*SEQ + j0)) * DM + h*DH;
        const float* Vg = V + ((size_t)(b*SEQ + j0)) * DM + h*DH;
        for (int i = tid; i < 64*32; i += 256) {
            int r = i >> 5, c = (i & 31) << 2;
            *(float4*)&sm[KS_OFF + r*132 + c] = *(const float4*)(Kg + (size_t)r*DM + c);
            *(float4*)&sm[VS_OFF + r*132 + c] = *(const float4*)(Vg + (size_t)r*DM + c);
        }
        __syncthreads();

        // S = Qs @ Ks^T
        float s[8][4];
#pragma unroll
        for (int i = 0; i < 8; i++)
#pragma unroll
            for (int j = 0; j < 4; j++) s[i][j] = 0.f;

        for (int k = 0; k < 128; k += 4) {
            float4 kv[4];
#pragma unroll
            for (int j = 0; j < 4; j++)
                kv[j] = *(const float4*)&sm[KS_OFF + (cS+j)*132 + k];
#pragma unroll
            for (int i = 0; i < 8; i++) {
                float4 qv = *(const float4*)&sm[QS_OFF + (r0+i)*132 + k];
#pragma unroll
                for (int j = 0; j < 4; j++)
                    s[i][j] += qv.x*kv[j].x + qv.y*kv[j].y
                             + qv.z*kv[j].z + qv.w*kv[j].w;
            }
        }

        if (j0 + 63 > i0) {   // only diagonal tiles need the causal mask
#pragma unroll
            for (int i = 0; i < 8; i++)
#pragma unroll
                for (int j = 0; j < 4; j++)
                    if (j0 + cS + j > i0 + r0 + i) s[i][j] = -1e30f;
        }

        float alpha[8];
#pragma unroll
        for (int i = 0; i < 8; i++) {
            float mx = fmaxf(fmaxf(s[i][0], s[i][1]), fmaxf(s[i][2], s[i][3]));
#pragma unroll
            for (int off = 8; off >= 1; off >>= 1)
                mx = fmaxf(mx, __shfl_xor_sync(0xffffffffu, mx, off));
            float mnew = fmaxf(m_r[i], mx);
            alpha[i] = __expf(m_r[i] - mnew);
            m_r[i] = mnew;
            float rs = 0.f;
#pragma unroll
            for (int j = 0; j < 4; j++) {
                s[i][j] = __expf(s[i][j] - mnew);
                rs += s[i][j];
            }
#pragma unroll
            for (int off = 8; off >= 1; off >>= 1)
                rs += __shfl_xor_sync(0xffffffffu, rs, off);
            l_r[i] = l_r[i]*alpha[i] + rs;
            *(float4*)&sm[PS_OFF + (r0+i)*68 + cS] =
                make_float4(s[i][0], s[i][1], s[i][2], s[i][3]);
        }
        __syncthreads();

        // O = O*alpha + Ps @ Vs
#pragma unroll
        for (int i = 0; i < 8; i++)
#pragma unroll
            for (int j = 0; j < 8; j++) o[i][j] *= alpha[i];

        for (int j = 0; j < 64; j++) {
            float4 v0 = *(const float4*)&sm[VS_OFF + j*132 + cO];
            float4 v1 = *(const float4*)&sm[VS_OFF + j*132 + cO + 4];
#pragma unroll
            for (int i = 0; i < 8; i++) {
                float p = sm[PS_OFF + (r0+i)*68 + j];
                o[i][0] += p*v0.x; o[i][1] += p*v0.y;
                o[i][2] += p*v0.z; o[i][3] += p*v0.w;
                o[i][4] += p*v1.x; o[i][5] += p*v1.y;
                o[i][6] += p*v1.z; o[i][7] += p*v1.w;
            }
        }
    }

    float* Og = O + ((size_t)(b*SEQ + i0)) * DM + h*DH;
#pragma unroll
    for (int i = 0; i < 8; i++) {
        float inv = 1.0f / l_r[i];
        float4 o0 = make_float4(o[i][0]*inv, o[i][1]*inv, o[i][2]*inv, o[i][3]*inv);
        float4 o1 = make_float4(o[i][4]*inv, o[i][5]*inv, o[i][6]*inv, o[i][7]*inv);
        *(float4*)(Og + (size_t)(r0+i)*DM + cO)     = o0;
        *(float4*)(Og + (size_t)(r0+i)*DM + cO + 4) = o1;
    }
}

// ---------------------------------------------------------------------------
extern "C" void kernel_launch(void* const* d_in, const int* in_sizes, int n_in,
                              void* d_out, int out_size)
{
    (void)in_sizes; (void)n_in; (void)out_size;
    const float* x    = (const float*)d_in[0];
    const float* Wq   = (const float*)d_in[1];
    const float* bq   = (const float*)d_in[2];
    const float* Wk   = (const float*)d_in[3];
    const float* bk   = (const float*)d_in[4];
    const float* Wv   = (const float*)d_in[5];
    const float* bv   = (const float*)d_in[6];
    const float* Wo   = (const float*)d_in[7];
    const float* bo   = (const float*)d_in[8];
    const float* sinT = (const float*)d_in[9];
    const float* cosT = (const float*)d_in[10];
    float* out = (float*)d_out;

    void *pq, *pk, *pv, *pa;
    cudaGetSymbolAddress(&pq, g_q);
    cudaGetSymbolAddress(&pk, g_k);
    cudaGetSymbolAddress(&pv, g_v);
    cudaGetSymbolAddress(&pa, g_att);
    float* q   = (float*)pq;
    float* k   = (float*)pk;
    float* v   = (float*)pv;
    float* att = (float*)pa;

    dim3 ggrid(DM/128, MTOT/128);   // (16, 32)
    sgemm_bias_kernel<<<ggrid, 256>>>(x, Wq, bq, q, DM, DM);
    sgemm_bias_kernel<<<ggrid, 256>>>(x, Wk, bk, k, DM, DM);
    sgemm_bias_kernel<<<ggrid, 256>>>(x, Wv, bv, v, DM, DM);

    rope_kernel<<<MTOT, 1024>>>(q, k, sinT, cosT);

    cudaFuncSetAttribute(flash_attn_kernel,
                         cudaFuncAttributeMaxDynamicSharedMemorySize,
                         SMEM_FLOATS * 4);
    flash_attn_kernel<<<dim3(SEQ/128, NHEADS, BATCH), 256, SMEM_FLOATS*4>>>(q, k, v, att);

    sgemm_bias_kernel<<<ggrid, 256>>>(att, Wo, bo, out, DM, DM);
}

// round 6
// speedup vs baseline: 1.7719x; 1.7719x over previous
#include <cuda_runtime.h>
#include <cuda_bf16.h>
#include <cstdint>

#define DM     2048
#define NHEADS 16
#define DH     128
#define BATCH  2
#define SEQ    2048
#define MTOT   (BATCH*SEQ)   // 4096

// Scratch (allocation-free): 4 x 33.5 MB
__device__ float g_q  [(size_t)MTOT * DM];
__device__ float g_k  [(size_t)MTOT * DM];
__device__ float g_v  [(size_t)MTOT * DM];
__device__ float g_att[(size_t)MTOT * DM];

// ===========================================================================
// Helpers (sm_80-compatible PTX only — NO tcgen05 on this harness's target)
// ===========================================================================
__device__ __forceinline__ uint32_t smem_u32(const void* p) {
    uint32_t a;
    asm("{ .reg .u64 t; cvta.to.shared.u64 t, %1; cvt.u32.u64 %0, t; }"
        : "=r"(a) : "l"(p));
    return a;
}
__device__ __forceinline__ uint32_t lds32(uint32_t a) {
    uint32_t v;
    asm volatile("ld.shared.b32 %0, [%1];" : "=r"(v) : "r"(a));
    return v;
}
__device__ __forceinline__ void sts64(uint32_t addr, uint32_t a, uint32_t b) {
    asm volatile("st.shared.v2.b32 [%0], {%1,%2};" :: "r"(addr), "r"(a), "r"(b) : "memory");
}
// split float4 -> hi/lo bf16x2 pairs (element0 in low 16 bits)
__device__ __forceinline__ void cvt_split(float4 v, uint32_t& h01, uint32_t& h23,
                                          uint32_t& l01, uint32_t& l23) {
    asm("cvt.rn.bf16x2.f32 %0, %1, %2;" : "=r"(h01) : "f"(v.y), "f"(v.x));
    asm("cvt.rn.bf16x2.f32 %0, %1, %2;" : "=r"(h23) : "f"(v.w), "f"(v.z));
    float f0 = __uint_as_float(h01 << 16);
    float f1 = __uint_as_float(h01 & 0xffff0000u);
    float f2 = __uint_as_float(h23 << 16);
    float f3 = __uint_as_float(h23 & 0xffff0000u);
    asm("cvt.rn.bf16x2.f32 %0, %1, %2;" : "=r"(l01) : "f"(v.y - f1), "f"(v.x - f0));
    asm("cvt.rn.bf16x2.f32 %0, %1, %2;" : "=r"(l23) : "f"(v.w - f3), "f"(v.z - f2));
}
// m16n8k16 row.col bf16 MMA, fp32 accumulate (in-place)
__device__ __forceinline__ void mma_bf16(float* d,
    uint32_t a0, uint32_t a1, uint32_t a2, uint32_t a3,
    uint32_t b0, uint32_t b1)
{
    asm volatile(
        "mma.sync.aligned.m16n8k16.row.col.f32.bf16.bf16.f32 "
        "{%0,%1,%2,%3}, {%4,%5,%6,%7}, {%8,%9}, {%0,%1,%2,%3};"
        : "+f"(d[0]), "+f"(d[1]), "+f"(d[2]), "+f"(d[3])
        : "r"(a0), "r"(a1), "r"(a2), "r"(a3), "r"(b0), "r"(b1));
}

// ===========================================================================
// Tensor-core GEMM: Y[M,N] = X[M,K] @ W[N,K]^T + bias (split-bf16 3-term, fp32)
// 128x128 tile/CTA, BK=32, 256 threads (8 warps, 2x4), double-buffered smem.
// Smem row stride 80B (32 bf16 + 8B pad) -> conflict-free fragment loads.
// ===========================================================================
#define SROW       80
#define A_HI_OFF   0
#define A_LO_OFF   (128*SROW)          // 10240
#define B_HI_OFF   (2*128*SROW)        // 20480
#define B_LO_OFF   (3*128*SROW)        // 30720
#define STAGE_B    (4*128*SROW)        // 40960
#define GEMM_SMEM_BYTES (2*STAGE_B)    // 81920

__device__ __forceinline__ void gemm_body(
    const float* __restrict__ X, const float* __restrict__ W,
    const float* __restrict__ bias, float* __restrict__ Y)
{
    extern __shared__ char smem[];
    const uint32_t sb = smem_u32(smem);
    const int tid = threadIdx.x;
    const int wid = tid >> 5;
    const int lid = tid & 31;
    const int wm  = wid >> 2;          // 0..1  (64 rows each)
    const int wn  = wid & 3;           // 0..3  (32 cols each)
    const int m0  = blockIdx.y * 128;
    const int n0  = blockIdx.x * 128;
    const int r   = lid >> 2;          // 0..7
    const int cw  = lid & 3;           // 0..3  (b32 word within 16B)

    float acc[4][4][4];
#pragma unroll
    for (int mi = 0; mi < 4; mi++)
#pragma unroll
        for (int ni = 0; ni < 4; ni++)
#pragma unroll
            for (int d = 0; d < 4; d++) acc[mi][ni][d] = 0.f;

    float4 av[4], bv[4];   // global prefetch buffers

    auto ldg = [&](int kc) {
        const float* Ag = X + (size_t)m0 * DM + kc * 32;
        const float* Bg = W + (size_t)n0 * DM + kc * 32;
#pragma unroll
        for (int ii = 0; ii < 4; ii++) {
            int i  = tid + ii * 256;   // 1024 float4 per tile
            int rr = i >> 3, c4 = i & 7;
            av[ii] = *(const float4*)(Ag + (size_t)rr * DM + c4 * 4);
            bv[ii] = *(const float4*)(Bg + (size_t)rr * DM + c4 * 4);
        }
    };
    auto sts_stage = [&](int s) {
        const uint32_t st = sb + s * STAGE_B;
#pragma unroll
        for (int ii = 0; ii < 4; ii++) {
            int i  = tid + ii * 256;
            int rr = i >> 3, c4 = i & 7;
            uint32_t off = rr * SROW + c4 * 8;
            uint32_t h01, h23, l01, l23;
            cvt_split(av[ii], h01, h23, l01, l23);
            sts64(st + A_HI_OFF + off, h01, h23);
            sts64(st + A_LO_OFF + off, l01, l23);
            cvt_split(bv[ii], h01, h23, l01, l23);
            sts64(st + B_HI_OFF + off, h01, h23);
            sts64(st + B_LO_OFF + off, l01, l23);
        }
    };
    auto compute = [&](int s) {
        const uint32_t st = sb + s * STAGE_B;
        const uint32_t abase = st + A_HI_OFF + (wm*64 + r) * SROW + cw * 4;
        const uint32_t bbase = st + B_HI_OFF + (wn*32 + r) * SROW + cw * 4;
#pragma unroll
        for (int kk = 0; kk < 2; kk++) {
            const uint32_t ko = kk * 32;   // 16 bf16 = 32 bytes
            uint32_t ah[4][4], bh[4][2], bl[4][2];
#pragma unroll
            for (int mi = 0; mi < 4; mi++) {
                uint32_t a = abase + mi * 16 * SROW + ko;
                ah[mi][0] = lds32(a);
                ah[mi][1] = lds32(a + 8*SROW);
                ah[mi][2] = lds32(a + 16);
                ah[mi][3] = lds32(a + 8*SROW + 16);
            }
#pragma unroll
            for (int ni = 0; ni < 4; ni++) {
                uint32_t b = bbase + ni * 8 * SROW + ko;
                bh[ni][0] = lds32(b);
                bh[ni][1] = lds32(b + 16);
                bl[ni][0] = lds32(b + (B_LO_OFF - B_HI_OFF));
                bl[ni][1] = lds32(b + (B_LO_OFF - B_HI_OFF) + 16);
            }
#pragma unroll
            for (int mi = 0; mi < 4; mi++)
#pragma unroll
                for (int ni = 0; ni < 4; ni++) {
                    mma_bf16(acc[mi][ni], ah[mi][0], ah[mi][1], ah[mi][2], ah[mi][3],
                             bh[ni][0], bh[ni][1]);
                    mma_bf16(acc[mi][ni], ah[mi][0], ah[mi][1], ah[mi][2], ah[mi][3],
                             bl[ni][0], bl[ni][1]);
                }
            uint32_t al[4][4];
#pragma unroll
            for (int mi = 0; mi < 4; mi++) {
                uint32_t a = abase + (A_LO_OFF - A_HI_OFF) + mi * 16 * SROW + ko;
                al[mi][0] = lds32(a);
                al[mi][1] = lds32(a + 8*SROW);
                al[mi][2] = lds32(a + 16);
                al[mi][3] = lds32(a + 8*SROW + 16);
            }
#pragma unroll
            for (int mi = 0; mi < 4; mi++)
#pragma unroll
                for (int ni = 0; ni < 4; ni++)
                    mma_bf16(acc[mi][ni], al[mi][0], al[mi][1], al[mi][2], al[mi][3],
                             bh[ni][0], bh[ni][1]);
        }
    };

    ldg(0); sts_stage(0);
    __syncthreads();
    for (int kc = 0; kc < 64; kc++) {
        const int s = kc & 1;
        if (kc < 63) ldg(kc + 1);
        compute(s);
        if (kc < 63) sts_stage(s ^ 1);
        __syncthreads();
    }

    // Epilogue: acc -> Y + bias
#pragma unroll
    for (int mi = 0; mi < 4; mi++) {
        const int row = m0 + wm*64 + mi*16 + r;
#pragma unroll
        for (int ni = 0; ni < 4; ni++) {
            const int col = n0 + wn*32 + ni*8 + 2*cw;
            float2 bb = *(const float2*)(bias + col);
            float2 v0 = make_float2(acc[mi][ni][0] + bb.x, acc[mi][ni][1] + bb.y);
            float2 v1 = make_float2(acc[mi][ni][2] + bb.x, acc[mi][ni][3] + bb.y);
            *(float2*)(Y + (size_t)row * DM + col)       = v0;
            *(float2*)(Y + (size_t)(row + 8) * DM + col) = v1;
        }
    }
}

__global__ __launch_bounds__(256) void gemm_tc_kernel(
    const float* __restrict__ X, const float* __restrict__ W,
    const float* __restrict__ bias, float* __restrict__ Y)
{
    gemm_body(X, W, bias, Y);
}

// Fused QKV: one launch, blockIdx.z selects weight/bias/output.
__global__ __launch_bounds__(256) void gemm_tc_qkv_kernel(
    const float* __restrict__ X,
    const float* __restrict__ Wq, const float* __restrict__ bq, float* __restrict__ Yq,
    const float* __restrict__ Wk, const float* __restrict__ bk, float* __restrict__ Yk,
    const float* __restrict__ Wv, const float* __restrict__ bv, float* __restrict__ Yv)
{
    const int z = blockIdx.z;
    const float* W = (z == 0) ? Wq : (z == 1) ? Wk : Wv;
    const float* b = (z == 0) ? bq : (z == 1) ? bk : bv;
    float*       Y = (z == 0) ? Yq : (z == 1) ? Yk : Yv;
    gemm_body(X, W, b, Y);
}

// ---------------------------------------------------------------------------
// RoPE in-place on Q and K, (B,T,H*DH) layout. 1024 threads = 16 heads x 64 pairs
// ---------------------------------------------------------------------------
__global__ void rope_kernel(float* __restrict__ q, float* __restrict__ k,
                            const float* __restrict__ sinT,
                            const float* __restrict__ cosT)
{
    int bt  = blockIdx.x;
    int t   = bt & (SEQ - 1);
    int tid = threadIdx.x;
    int h = tid >> 6, d = tid & 63;
    float s = sinT[t*64 + d];
    float c = cosT[t*64 + d];
    size_t base = (size_t)bt * DM + h*DH + d;
    float q1 = q[base], q2 = q[base + 64];
    q[base]      = q1*c - q2*s;
    q[base + 64] = q1*s + q2*c;
    float k1 = k[base], k2 = k[base + 64];
    k[base]      = k1*c - k2*s;
    k[base + 64] = k1*s + k2*c;
}

// ---------------------------------------------------------------------------
// Flash attention (causal), fp32. BM=128 q-rows, BN=64 kv-rows, 256 threads.
// ---------------------------------------------------------------------------
#define QS_OFF 0
#define KS_OFF (128*132)
#define VS_OFF (KS_OFF + 64*132)
#define PS_OFF (VS_OFF + 64*132)
#define SMEM_FLOATS (PS_OFF + 128*68)

__global__ __launch_bounds__(256) void flash_attn_kernel(
    const float* __restrict__ Q, const float* __restrict__ K,
    const float* __restrict__ V, float* __restrict__ O)
{
    extern __shared__ float sm[];
    const int tid = threadIdx.x;
    const int i0 = blockIdx.x * 128;
    const int h  = blockIdx.y;
    const int b  = blockIdx.z;
    const int tx = tid & 15;
    const int ty = tid >> 4;
    const int r0 = ty * 8;
    const int cS = tx * 4;
    const int cO = tx * 8;
    const float scale = 0.08838834764831845f;

    const float* Qg = Q + ((size_t)(b*SEQ + i0)) * DM + h*DH;
    for (int i = tid; i < 128*32; i += 256) {
        int r = i >> 5, c = (i & 31) << 2;
        float4 v = *(const float4*)(Qg + (size_t)r*DM + c);
        v.x *= scale; v.y *= scale; v.z *= scale; v.w *= scale;
        *(float4*)&sm[QS_OFF + r*132 + c] = v;
    }

    float m_r[8], l_r[8], o[8][8];
#pragma unroll
    for (int i = 0; i < 8; i++) {
        m_r[i] = -1e30f; l_r[i] = 0.f;
#pragma unroll
        for (int j = 0; j < 8; j++) o[i][j] = 0.f;
    }

    const int ntiles = (i0 >> 6) + 2;
    for (int jt = 0; jt < ntiles; jt++) {
        const int j0 = jt * 64;
        __syncthreads();
        const float* Kg = K + ((size_t)(b*SEQ + j0)) * DM + h*DH;
        const float* Vg = V + ((size_t)(b*SEQ + j0)) * DM + h*DH;
        for (int i = tid; i < 64*32; i += 256) {
            int r = i >> 5, c = (i & 31) << 2;
            *(float4*)&sm[KS_OFF + r*132 + c] = *(const float4*)(Kg + (size_t)r*DM + c);
            *(float4*)&sm[VS_OFF + r*132 + c] = *(const float4*)(Vg + (size_t)r*DM + c);
        }
        __syncthreads();

        float s[8][4];
#pragma unroll
        for (int i = 0; i < 8; i++)
#pragma unroll
            for (int j = 0; j < 4; j++) s[i][j] = 0.f;

        for (int k = 0; k < 128; k += 4) {
            float4 kv[4];
#pragma unroll
            for (int j = 0; j < 4; j++)
                kv[j] = *(const float4*)&sm[KS_OFF + (cS+j)*132 + k];
#pragma unroll
            for (int i = 0; i < 8; i++) {
                float4 qv = *(const float4*)&sm[QS_OFF + (r0+i)*132 + k];
#pragma unroll
                for (int j = 0; j < 4; j++)
                    s[i][j] += qv.x*kv[j].x + qv.y*kv[j].y
                             + qv.z*kv[j].z + qv.w*kv[j].w;
            }
        }

        if (j0 + 63 > i0) {
#pragma unroll
            for (int i = 0; i < 8; i++)
#pragma unroll
                for (int j = 0; j < 4; j++)
                    if (j0 + cS + j > i0 + r0 + i) s[i][j] = -1e30f;
        }

        float alpha[8];
#pragma unroll
        for (int i = 0; i < 8; i++) {
            float mx = fmaxf(fmaxf(s[i][0], s[i][1]), fmaxf(s[i][2], s[i][3]));
#pragma unroll
            for (int off = 8; off >= 1; off >>= 1)
                mx = fmaxf(mx, __shfl_xor_sync(0xffffffffu, mx, off));
            float mnew = fmaxf(m_r[i], mx);
            alpha[i] = __expf(m_r[i] - mnew);
            m_r[i] = mnew;
            float rs = 0.f;
#pragma unroll
            for (int j = 0; j < 4; j++) {
                s[i][j] = __expf(s[i][j] - mnew);
                rs += s[i][j];
            }
#pragma unroll
            for (int off = 8; off >= 1; off >>= 1)
                rs += __shfl_xor_sync(0xffffffffu, rs, off);
            l_r[i] = l_r[i]*alpha[i] + rs;
            *(float4*)&sm[PS_OFF + (r0+i)*68 + cS] =
                make_float4(s[i][0], s[i][1], s[i][2], s[i][3]);
        }
        __syncthreads();

#pragma unroll
        for (int i = 0; i < 8; i++)
#pragma unroll
            for (int j = 0; j < 8; j++) o[i][j] *= alpha[i];

        for (int j = 0; j < 64; j++) {
            float4 v0 = *(const float4*)&sm[VS_OFF + j*132 + cO];
            float4 v1 = *(const float4*)&sm[VS_OFF + j*132 + cO + 4];
#pragma unroll
            for (int i = 0; i < 8; i++) {
                float p = sm[PS_OFF + (r0+i)*68 + j];
                o[i][0] += p*v0.x; o[i][1] += p*v0.y;
                o[i][2] += p*v0.z; o[i][3] += p*v0.w;
                o[i][4] += p*v1.x; o[i][5] += p*v1.y;
                o[i][6] += p*v1.z; o[i][7] += p*v1.w;
            }
        }
    }

    float* Og = O + ((size_t)(b*SEQ + i0)) * DM + h*DH;
#pragma unroll
    for (int i = 0; i < 8; i++) {
        float inv = 1.0f / l_r[i];
        float4 o0 = make_float4(o[i][0]*inv, o[i][1]*inv, o[i][2]*inv, o[i][3]*inv);
        float4 o1 = make_float4(o[i][4]*inv, o[i][5]*inv, o[i][6]*inv, o[i][7]*inv);
        *(float4*)(Og + (size_t)(r0+i)*DM + cO)     = o0;
        *(float4*)(Og + (size_t)(r0+i)*DM + cO + 4) = o1;
    }
}

// ---------------------------------------------------------------------------
extern "C" void kernel_launch(void* const* d_in, const int* in_sizes, int n_in,
                              void* d_out, int out_size)
{
    (void)in_sizes; (void)n_in; (void)out_size;
    const float* x    = (const float*)d_in[0];
    const float* Wq   = (const float*)d_in[1];
    const float* bq   = (const float*)d_in[2];
    const float* Wk   = (const float*)d_in[3];
    const float* bk   = (const float*)d_in[4];
    const float* Wv   = (const float*)d_in[5];
    const float* bv   = (const float*)d_in[6];
    const float* Wo   = (const float*)d_in[7];
    const float* bo   = (const float*)d_in[8];
    const float* sinT = (const float*)d_in[9];
    const float* cosT = (const float*)d_in[10];
    float* out = (float*)d_out;

    void *pq, *pk, *pv, *pa;
    cudaGetSymbolAddress(&pq, g_q);
    cudaGetSymbolAddress(&pk, g_k);
    cudaGetSymbolAddress(&pv, g_v);
    cudaGetSymbolAddress(&pa, g_att);
    float* q   = (float*)pq;
    float* k   = (float*)pk;
    float* v   = (float*)pv;
    float* att = (float*)pa;

    cudaFuncSetAttribute(gemm_tc_kernel,
                         cudaFuncAttributeMaxDynamicSharedMemorySize,
                         GEMM_SMEM_BYTES);
    cudaFuncSetAttribute(gemm_tc_qkv_kernel,
                         cudaFuncAttributeMaxDynamicSharedMemorySize,
                         GEMM_SMEM_BYTES);
    cudaFuncSetAttribute(flash_attn_kernel,
                         cudaFuncAttributeMaxDynamicSharedMemorySize,
                         SMEM_FLOATS * 4);

    dim3 qkv_grid(DM/128, MTOT/128, 3);   // (16, 32, 3)
    gemm_tc_qkv_kernel<<<qkv_grid, 256, GEMM_SMEM_BYTES>>>(
        x, Wq, bq, q, Wk, bk, k, Wv, bv, v);

    rope_kernel<<<MTOT, 1024>>>(q, k, sinT, cosT);

    flash_attn_kernel<<<dim3(SEQ/128, NHEADS, BATCH), 256, SMEM_FLOATS*4>>>(q, k, v, att);

    dim3 ggrid(DM/128, MTOT/128);   // (16, 32)
    gemm_tc_kernel<<<ggrid, 256, GEMM_SMEM_BYTES>>>(att, Wo, bo, out);
}

// round 7
// speedup vs baseline: 3.2708x; 1.8459x over previous
#include <cuda_runtime.h>
#include <cuda_bf16.h>
#include <cstdint>

#define DM     2048
#define NHEADS 16
#define DH     128
#define BATCH  2
#define SEQ    2048
#define MTOT   (BATCH*SEQ)   // 4096

// Scratch (allocation-free): 4 x 33.5 MB
__device__ float g_q  [(size_t)MTOT * DM];
__device__ float g_k  [(size_t)MTOT * DM];
__device__ float g_v  [(size_t)MTOT * DM];
__device__ float g_att[(size_t)MTOT * DM];

// ===========================================================================
// Helpers (sm_80-compatible PTX only — NO tcgen05 on this harness's target)
// ===========================================================================
__device__ __forceinline__ uint32_t smem_u32(const void* p) {
    uint32_t a;
    asm("{ .reg .u64 t; cvta.to.shared.u64 t, %1; cvt.u32.u64 %0, t; }"
        : "=r"(a) : "l"(p));
    return a;
}
__device__ __forceinline__ uint32_t lds32(uint32_t a) {
    uint32_t v;
    asm volatile("ld.shared.b32 %0, [%1];" : "=r"(v) : "r"(a));
    return v;
}
__device__ __forceinline__ void sts64(uint32_t addr, uint32_t a, uint32_t b) {
    asm volatile("st.shared.v2.b32 [%0], {%1,%2};" :: "r"(addr), "r"(a), "r"(b) : "memory");
}
__device__ __forceinline__ uint32_t pack_bf16(float e0, float e1) {
    uint32_t r;
    asm("cvt.rn.bf16x2.f32 %0, %1, %2;" : "=r"(r) : "f"(e1), "f"(e0));
    return r;
}
__device__ __forceinline__ float ex2f(float x) {
    float y; asm("ex2.approx.f32 %0, %1;" : "=f"(y) : "f"(x)); return y;
}
__device__ __forceinline__ void ldsm4t(uint32_t addr, uint32_t& r0, uint32_t& r1,
                                       uint32_t& r2, uint32_t& r3) {
    asm volatile("ldmatrix.sync.aligned.m8n8.x4.trans.shared.b16 {%0,%1,%2,%3}, [%4];"
        : "=r"(r0), "=r"(r1), "=r"(r2), "=r"(r3) : "r"(addr));
}
// split float4 -> hi/lo bf16x2 pairs (element0 in low 16 bits)
__device__ __forceinline__ void cvt_split(float4 v, uint32_t& h01, uint32_t& h23,
                                          uint32_t& l01, uint32_t& l23) {
    asm("cvt.rn.bf16x2.f32 %0, %1, %2;" : "=r"(h01) : "f"(v.y), "f"(v.x));
    asm("cvt.rn.bf16x2.f32 %0, %1, %2;" : "=r"(h23) : "f"(v.w), "f"(v.z));
    float f0 = __uint_as_float(h01 << 16);
    float f1 = __uint_as_float(h01 & 0xffff0000u);
    float f2 = __uint_as_float(h23 << 16);
    float f3 = __uint_as_float(h23 & 0xffff0000u);
    asm("cvt.rn.bf16x2.f32 %0, %1, %2;" : "=r"(l01) : "f"(v.y - f1), "f"(v.x - f0));
    asm("cvt.rn.bf16x2.f32 %0, %1, %2;" : "=r"(l23) : "f"(v.w - f3), "f"(v.z - f2));
}
// m16n8k16 row.col bf16 MMA, fp32 accumulate (in-place)
__device__ __forceinline__ void mma_bf16(float* d,
    uint32_t a0, uint32_t a1, uint32_t a2, uint32_t a3,
    uint32_t b0, uint32_t b1)
{
    asm volatile(
        "mma.sync.aligned.m16n8k16.row.col.f32.bf16.bf16.f32 "
        "{%0,%1,%2,%3}, {%4,%5,%6,%7}, {%8,%9}, {%0,%1,%2,%3};"
        : "+f"(d[0]), "+f"(d[1]), "+f"(d[2]), "+f"(d[3])
        : "r"(a0), "r"(a1), "r"(a2), "r"(a3), "r"(b0), "r"(b1));
}

// ===========================================================================
// Tensor-core GEMM: Y[M,N] = X[M,K] @ W[N,K]^T + bias (split-bf16 3-term, fp32)
// 128x128 tile/CTA, BK=32, 256 threads (8 warps, 2x4), double-buffered smem.
// ===========================================================================
#define SROW       80
#define A_HI_OFF   0
#define A_LO_OFF   (128*SROW)
#define B_HI_OFF   (2*128*SROW)
#define B_LO_OFF   (3*128*SROW)
#define STAGE_B    (4*128*SROW)
#define GEMM_SMEM_BYTES (2*STAGE_B)

__device__ __forceinline__ void gemm_body(
    const float* __restrict__ X, const float* __restrict__ W,
    const float* __restrict__ bias, float* __restrict__ Y)
{
    extern __shared__ char smem[];
    const uint32_t sb = smem_u32(smem);
    const int tid = threadIdx.x;
    const int wid = tid >> 5;
    const int lid = tid & 31;
    const int wm  = wid >> 2;
    const int wn  = wid & 3;
    const int m0  = blockIdx.y * 128;
    const int n0  = blockIdx.x * 128;
    const int r   = lid >> 2;
    const int cw  = lid & 3;

    float acc[4][4][4];
#pragma unroll
    for (int mi = 0; mi < 4; mi++)
#pragma unroll
        for (int ni = 0; ni < 4; ni++)
#pragma unroll
            for (int d = 0; d < 4; d++) acc[mi][ni][d] = 0.f;

    float4 av[4], bv[4];

    auto ldg = [&](int kc) {
        const float* Ag = X + (size_t)m0 * DM + kc * 32;
        const float* Bg = W + (size_t)n0 * DM + kc * 32;
#pragma unroll
        for (int ii = 0; ii < 4; ii++) {
            int i  = tid + ii * 256;
            int rr = i >> 3, c4 = i & 7;
            av[ii] = *(const float4*)(Ag + (size_t)rr * DM + c4 * 4);
            bv[ii] = *(const float4*)(Bg + (size_t)rr * DM + c4 * 4);
        }
    };
    auto sts_stage = [&](int s) {
        const uint32_t st = sb + s * STAGE_B;
#pragma unroll
        for (int ii = 0; ii < 4; ii++) {
            int i  = tid + ii * 256;
            int rr = i >> 3, c4 = i & 7;
            uint32_t off = rr * SROW + c4 * 8;
            uint32_t h01, h23, l01, l23;
            cvt_split(av[ii], h01, h23, l01, l23);
            sts64(st + A_HI_OFF + off, h01, h23);
            sts64(st + A_LO_OFF + off, l01, l23);
            cvt_split(bv[ii], h01, h23, l01, l23);
            sts64(st + B_HI_OFF + off, h01, h23);
            sts64(st + B_LO_OFF + off, l01, l23);
        }
    };
    auto compute = [&](int s) {
        const uint32_t st = sb + s * STAGE_B;
        const uint32_t abase = st + A_HI_OFF + (wm*64 + r) * SROW + cw * 4;
        const uint32_t bbase = st + B_HI_OFF + (wn*32 + r) * SROW + cw * 4;
#pragma unroll
        for (int kk = 0; kk < 2; kk++) {
            const uint32_t ko = kk * 32;
            uint32_t ah[4][4], bh[4][2], bl[4][2];
#pragma unroll
            for (int mi = 0; mi < 4; mi++) {
                uint32_t a = abase + mi * 16 * SROW + ko;
                ah[mi][0] = lds32(a);
                ah[mi][1] = lds32(a + 8*SROW);
                ah[mi][2] = lds32(a + 16);
                ah[mi][3] = lds32(a + 8*SROW + 16);
            }
#pragma unroll
            for (int ni = 0; ni < 4; ni++) {
                uint32_t b = bbase + ni * 8 * SROW + ko;
                bh[ni][0] = lds32(b);
                bh[ni][1] = lds32(b + 16);
                bl[ni][0] = lds32(b + (B_LO_OFF - B_HI_OFF));
                bl[ni][1] = lds32(b + (B_LO_OFF - B_HI_OFF) + 16);
            }
#pragma unroll
            for (int mi = 0; mi < 4; mi++)
#pragma unroll
                for (int ni = 0; ni < 4; ni++) {
                    mma_bf16(acc[mi][ni], ah[mi][0], ah[mi][1], ah[mi][2], ah[mi][3],
                             bh[ni][0], bh[ni][1]);
                    mma_bf16(acc[mi][ni], ah[mi][0], ah[mi][1], ah[mi][2], ah[mi][3],
                             bl[ni][0], bl[ni][1]);
                }
            uint32_t al[4][4];
#pragma unroll
            for (int mi = 0; mi < 4; mi++) {
                uint32_t a = abase + (A_LO_OFF - A_HI_OFF) + mi * 16 * SROW + ko;
                al[mi][0] = lds32(a);
                al[mi][1] = lds32(a + 8*SROW);
                al[mi][2] = lds32(a + 16);
                al[mi][3] = lds32(a + 8*SROW + 16);
            }
#pragma unroll
            for (int mi = 0; mi < 4; mi++)
#pragma unroll
                for (int ni = 0; ni < 4; ni++)
                    mma_bf16(acc[mi][ni], al[mi][0], al[mi][1], al[mi][2], al[mi][3],
                             bh[ni][0], bh[ni][1]);
        }
    };

    ldg(0); sts_stage(0);
    __syncthreads();
    for (int kc = 0; kc < 64; kc++) {
        const int s = kc & 1;
        if (kc < 63) ldg(kc + 1);
        compute(s);
        if (kc < 63) sts_stage(s ^ 1);
        __syncthreads();
    }

#pragma unroll
    for (int mi = 0; mi < 4; mi++) {
        const int row = m0 + wm*64 + mi*16 + r;
#pragma unroll
        for (int ni = 0; ni < 4; ni++) {
            const int col = n0 + wn*32 + ni*8 + 2*cw;
            float2 bb = *(const float2*)(bias + col);
            float2 v0 = make_float2(acc[mi][ni][0] + bb.x, acc[mi][ni][1] + bb.y);
            float2 v1 = make_float2(acc[mi][ni][2] + bb.x, acc[mi][ni][3] + bb.y);
            *(float2*)(Y + (size_t)row * DM + col)       = v0;
            *(float2*)(Y + (size_t)(row + 8) * DM + col) = v1;
        }
    }
}

__global__ __launch_bounds__(256) void gemm_tc_kernel(
    const float* __restrict__ X, const float* __restrict__ W,
    const float* __restrict__ bias, float* __restrict__ Y)
{
    gemm_body(X, W, bias, Y);
}

__global__ __launch_bounds__(256) void gemm_tc_qkv_kernel(
    const float* __restrict__ X,
    const float* __restrict__ Wq, const float* __restrict__ bq, float* __restrict__ Yq,
    const float* __restrict__ Wk, const float* __restrict__ bk, float* __restrict__ Yk,
    const float* __restrict__ Wv, const float* __restrict__ bv, float* __restrict__ Yv)
{
    const int z = blockIdx.z;
    const float* W = (z == 0) ? Wq : (z == 1) ? Wk : Wv;
    const float* b = (z == 0) ? bq : (z == 1) ? bk : bv;
    float*       Y = (z == 0) ? Yq : (z == 1) ? Yk : Yv;
    gemm_body(X, W, b, Y);
}

// ---------------------------------------------------------------------------
// RoPE in-place on Q and K
// ---------------------------------------------------------------------------
__global__ void rope_kernel(float* __restrict__ q, float* __restrict__ k,
                            const float* __restrict__ sinT,
                            const float* __restrict__ cosT)
{
    int bt  = blockIdx.x;
    int t   = bt & (SEQ - 1);
    int tid = threadIdx.x;
    int h = tid >> 6, d = tid & 63;
    float s = sinT[t*64 + d];
    float c = cosT[t*64 + d];
    size_t base = (size_t)bt * DM + h*DH + d;
    float q1 = q[base], q2 = q[base + 64];
    q[base]      = q1*c - q2*s;
    q[base + 64] = q1*s + q2*c;
    float k1 = k[base], k2 = k[base + 64];
    k[base]      = k1*c - k2*s;
    k[base + 64] = k1*s + k2*c;
}

// ===========================================================================
// Tensor-core flash attention (causal), split-bf16 3-term, exp2-domain softmax
// BM=128 q-rows (8 warps x m16), BN=64 kv, 256 threads.
// Smem: Q/K/V hi+lo bf16, row stride 272B (128 bf16 + 16B pad; conflict-free).
// ===========================================================================
#define FROW    272
#define QH_OFF  0
#define QL_OFF  (128*FROW)
#define KH_OFF  (2*128*FROW)
#define KL_OFF  (KH_OFF + 64*FROW)
#define VH_OFF  (KL_OFF + 64*FROW)
#define VL_OFF  (VH_OFF + 64*FROW)
#define FA_SMEM (VL_OFF + 64*FROW)   // 139264 bytes

__global__ __launch_bounds__(256) void flash_tc_kernel(
    const float* __restrict__ Q, const float* __restrict__ K,
    const float* __restrict__ V, float* __restrict__ O)
{
    extern __shared__ char smc[];
    const uint32_t sb = smem_u32(smc);
    const int tid = threadIdx.x;
    const int wid = tid >> 5;
    const int lid = tid & 31;
    const int r   = lid >> 2;
    const int cw  = lid & 3;
    const int i0  = blockIdx.x * 128;
    const int h   = blockIdx.y;
    const int b   = blockIdx.z;
    // 1/sqrt(128) * log2(e): softmax runs in exp2 domain
    const float qscale = 0.08838834764831845f * 1.4426950408889634f;

    // Load + scale + split Q tile (128 x 128)
    const float* Qg = Q + ((size_t)(b*SEQ + i0)) * DM + h*DH;
#pragma unroll
    for (int ii = 0; ii < 16; ii++) {
        int i  = tid + ii * 256;
        int rr = i >> 5, c4 = i & 31;
        float4 v = *(const float4*)(Qg + (size_t)rr * DM + c4 * 4);
        v.x *= qscale; v.y *= qscale; v.z *= qscale; v.w *= qscale;
        uint32_t h01, h23, l01, l23;
        cvt_split(v, h01, h23, l01, l23);
        uint32_t off = rr * FROW + c4 * 8;
        sts64(sb + QH_OFF + off, h01, h23);
        sts64(sb + QL_OFF + off, l01, l23);
    }

    float o[16][4];
#pragma unroll
    for (int t = 0; t < 16; t++)
#pragma unroll
        for (int d = 0; d < 4; d++) o[t][d] = 0.f;
    float m0 = -1e30f, m1 = -1e30f, l0 = 0.f, l1 = 0.f;

    const int row0 = i0 + 16*wid + r;   // global q row (within seq)
    const int row1 = row0 + 8;

    const int ntiles = (i0 >> 6) + 2;
    for (int jt = 0; jt < ntiles; jt++) {
        const int j0 = jt * 64;
        __syncthreads();   // prior tile's smem reads done
        // Fill K/V tiles (64 x 128 each), hi/lo split
        const float* Kg = K + ((size_t)(b*SEQ + j0)) * DM + h*DH;
        const float* Vg = V + ((size_t)(b*SEQ + j0)) * DM + h*DH;
#pragma unroll
        for (int ii = 0; ii < 8; ii++) {
            int i  = tid + ii * 256;
            int rr = i >> 5, c4 = i & 31;
            uint32_t off = rr * FROW + c4 * 8;
            uint32_t h01, h23, l01, l23;
            float4 kv = *(const float4*)(Kg + (size_t)rr * DM + c4 * 4);
            cvt_split(kv, h01, h23, l01, l23);
            sts64(sb + KH_OFF + off, h01, h23);
            sts64(sb + KL_OFF + off, l01, l23);
            float4 vv = *(const float4*)(Vg + (size_t)rr * DM + c4 * 4);
            cvt_split(vv, h01, h23, l01, l23);
            sts64(sb + VH_OFF + off, h01, h23);
            sts64(sb + VL_OFF + off, l01, l23);
        }
        __syncthreads();

        if (j0 <= i0 + 16*wid + 15) {   // warp has unmasked work in this tile
            // ---- S = Q Kt (3-term split-bf16), fragments in registers ----
            float s[8][4];
#pragma unroll
            for (int t = 0; t < 8; t++)
#pragma unroll
                for (int d = 0; d < 4; d++) s[t][d] = 0.f;

            const uint32_t qa = sb + QH_OFF + (16*wid + r) * FROW + cw * 4;
            const uint32_t kb = sb + KH_OFF + r * FROW + cw * 4;
#pragma unroll
            for (int kk = 0; kk < 8; kk++) {
                const uint32_t ko = kk * 32;
                uint32_t ah0 = lds32(qa + ko);
                uint32_t ah1 = lds32(qa + ko + 8*FROW);
                uint32_t ah2 = lds32(qa + ko + 16);
                uint32_t ah3 = lds32(qa + ko + 8*FROW + 16);
                uint32_t al0 = lds32(qa + ko + (QL_OFF - QH_OFF));
                uint32_t al1 = lds32(qa + ko + (QL_OFF - QH_OFF) + 8*FROW);
                uint32_t al2 = lds32(qa + ko + (QL_OFF - QH_OFF) + 16);
                uint32_t al3 = lds32(qa + ko + (QL_OFF - QH_OFF) + 8*FROW + 16);
#pragma unroll
                for (int t = 0; t < 8; t++) {
                    uint32_t kbt = kb + t * 8 * FROW + ko;
                    uint32_t bh0 = lds32(kbt);
                    uint32_t bh1 = lds32(kbt + 16);
                    uint32_t bl0 = lds32(kbt + (KL_OFF - KH_OFF));
                    uint32_t bl1 = lds32(kbt + (KL_OFF - KH_OFF) + 16);
                    mma_bf16(s[t], ah0, ah1, ah2, ah3, bh0, bh1);
                    mma_bf16(s[t], ah0, ah1, ah2, ah3, bl0, bl1);
                    mma_bf16(s[t], al0, al1, al2, al3, bh0, bh1);
                }
            }

            // ---- causal mask (diagonal-adjacent tiles only) ----
            if (j0 + 63 > i0 + 16*wid) {
#pragma unroll
                for (int t = 0; t < 8; t++) {
                    int c0 = j0 + t*8 + 2*cw;
                    if (c0     > row0) s[t][0] = -1e30f;
                    if (c0 + 1 > row0) s[t][1] = -1e30f;
                    if (c0     > row1) s[t][2] = -1e30f;
                    if (c0 + 1 > row1) s[t][3] = -1e30f;
                }
            }

            // ---- online softmax (exp2 domain), quad-lane row reductions ----
            float mx0 = -1e30f, mx1 = -1e30f;
#pragma unroll
            for (int t = 0; t < 8; t++) {
                mx0 = fmaxf(mx0, fmaxf(s[t][0], s[t][1]));
                mx1 = fmaxf(mx1, fmaxf(s[t][2], s[t][3]));
            }
            mx0 = fmaxf(mx0, __shfl_xor_sync(0xffffffffu, mx0, 1));
            mx0 = fmaxf(mx0, __shfl_xor_sync(0xffffffffu, mx0, 2));
            mx1 = fmaxf(mx1, __shfl_xor_sync(0xffffffffu, mx1, 1));
            mx1 = fmaxf(mx1, __shfl_xor_sync(0xffffffffu, mx1, 2));
            float mn0 = fmaxf(m0, mx0), mn1 = fmaxf(m1, mx1);
            float al_0 = ex2f(m0 - mn0), al_1 = ex2f(m1 - mn1);
            m0 = mn0; m1 = mn1;
            float rs0 = 0.f, rs1 = 0.f;
#pragma unroll
            for (int t = 0; t < 8; t++) {
                s[t][0] = ex2f(s[t][0] - mn0);
                s[t][1] = ex2f(s[t][1] - mn0);
                s[t][2] = ex2f(s[t][2] - mn1);
                s[t][3] = ex2f(s[t][3] - mn1);
                rs0 += s[t][0] + s[t][1];
                rs1 += s[t][2] + s[t][3];
            }
            rs0 += __shfl_xor_sync(0xffffffffu, rs0, 1);
            rs0 += __shfl_xor_sync(0xffffffffu, rs0, 2);
            rs1 += __shfl_xor_sync(0xffffffffu, rs1, 1);
            rs1 += __shfl_xor_sync(0xffffffffu, rs1, 2);
            l0 = l0 * al_0 + rs0;
            l1 = l1 * al_1 + rs1;
#pragma unroll
            for (int t = 0; t < 16; t++) {
                o[t][0] *= al_0; o[t][1] *= al_0;
                o[t][2] *= al_1; o[t][3] *= al_1;
            }

            // ---- pack P into A-fragments (hi/lo) ----
            uint32_t aph[4][4], apl[4][4];
#pragma unroll
            for (int kk = 0; kk < 4; kk++) {
#pragma unroll
                for (int half = 0; half < 2; half++) {
                    int t = 2*kk + half;
                    uint32_t hA = pack_bf16(s[t][0], s[t][1]);
                    uint32_t hB = pack_bf16(s[t][2], s[t][3]);
                    float h0 = __uint_as_float(hA << 16);
                    float h1 = __uint_as_float(hA & 0xffff0000u);
                    float h2 = __uint_as_float(hB << 16);
                    float h3 = __uint_as_float(hB & 0xffff0000u);
                    aph[kk][2*half]   = hA;
                    aph[kk][2*half+1] = hB;
                    apl[kk][2*half]   = pack_bf16(s[t][0]-h0, s[t][1]-h1);
                    apl[kk][2*half+1] = pack_bf16(s[t][2]-h2, s[t][3]-h3);
                }
            }

            // ---- O += P V (V fragments via ldmatrix.trans) ----
            const uint32_t vrow = sb + VH_OFF + (lid & 15) * FROW + ((lid >> 4) << 4);
#pragma unroll
            for (int kk = 0; kk < 4; kk++) {
                const uint32_t vk = vrow + kk * 16 * FROW;
#pragma unroll
                for (int tp = 0; tp < 8; tp++) {
                    uint32_t vh0, vh1, vh2, vh3, vl0, vl1, vl2, vl3;
                    ldsm4t(vk + tp * 32, vh0, vh1, vh2, vh3);
                    ldsm4t(vk + tp * 32 + (VL_OFF - VH_OFF), vl0, vl1, vl2, vl3);
                    mma_bf16(o[2*tp],   aph[kk][0], aph[kk][1], aph[kk][2], aph[kk][3], vh0, vh1);
                    mma_bf16(o[2*tp],   aph[kk][0], aph[kk][1], aph[kk][2], aph[kk][3], vl0, vl1);
                    mma_bf16(o[2*tp],   apl[kk][0], apl[kk][1], apl[kk][2], apl[kk][3], vh0, vh1);
                    mma_bf16(o[2*tp+1], aph[kk][0], aph[kk][1], aph[kk][2], aph[kk][3], vh2, vh3);
                    mma_bf16(o[2*tp+1], aph[kk][0], aph[kk][1], aph[kk][2], aph[kk][3], vl2, vl3);
                    mma_bf16(o[2*tp+1], apl[kk][0], apl[kk][1], apl[kk][2], apl[kk][3], vh2, vh3);
                }
            }
        }
    }

    // ---- epilogue: normalize and store ----
    const float inv0 = 1.0f / l0;
    const float inv1 = 1.0f / l1;
    float* Og = O + ((size_t)(b*SEQ + row0)) * DM + h*DH;
#pragma unroll
    for (int t = 0; t < 16; t++) {
        const int col = t*8 + 2*cw;
        *(float2*)(Og + col) =
            make_float2(o[t][0]*inv0, o[t][1]*inv0);
        *(float2*)(Og + 8*DM + col) =
            make_float2(o[t][2]*inv1, o[t][3]*inv1);
    }
}

// ---------------------------------------------------------------------------
extern "C" void kernel_launch(void* const* d_in, const int* in_sizes, int n_in,
                              void* d_out, int out_size)
{
    (void)in_sizes; (void)n_in; (void)out_size;
    const float* x    = (const float*)d_in[0];
    const float* Wq   = (const float*)d_in[1];
    const float* bq   = (const float*)d_in[2];
    const float* Wk   = (const float*)d_in[3];
    const float* bk   = (const float*)d_in[4];
    const float* Wv   = (const float*)d_in[5];
    const float* bv   = (const float*)d_in[6];
    const float* Wo   = (const float*)d_in[7];
    const float* bo   = (const float*)d_in[8];
    const float* sinT = (const float*)d_in[9];
    const float* cosT = (const float*)d_in[10];
    float* out = (float*)d_out;

    void *pq, *pk, *pv, *pa;
    cudaGetSymbolAddress(&pq, g_q);
    cudaGetSymbolAddress(&pk, g_k);
    cudaGetSymbolAddress(&pv, g_v);
    cudaGetSymbolAddress(&pa, g_att);
    float* q   = (float*)pq;
    float* k   = (float*)pk;
    float* v   = (float*)pv;
    float* att = (float*)pa;

    cudaFuncSetAttribute(gemm_tc_kernel,
                         cudaFuncAttributeMaxDynamicSharedMemorySize,
                         GEMM_SMEM_BYTES);
    cudaFuncSetAttribute(gemm_tc_qkv_kernel,
                         cudaFuncAttributeMaxDynamicSharedMemorySize,
                         GEMM_SMEM_BYTES);
    cudaFuncSetAttribute(flash_tc_kernel,
                         cudaFuncAttributeMaxDynamicSharedMemorySize,
                         FA_SMEM);

    dim3 qkv_grid(DM/128, MTOT/128, 3);
    gemm_tc_qkv_kernel<<<qkv_grid, 256, GEMM_SMEM_BYTES>>>(
        x, Wq, bq, q, Wk, bk, k, Wv, bv, v);

    rope_kernel<<<MTOT, 1024>>>(q, k, sinT, cosT);

    flash_tc_kernel<<<dim3(SEQ/128, NHEADS, BATCH), 256, FA_SMEM>>>(q, k, v, att);

    dim3 ggrid(DM/128, MTOT/128);
    gemm_tc_kernel<<<ggrid, 256, GEMM_SMEM_BYTES>>>(att, Wo, bo, out);
}

// round 8
// speedup vs baseline: 5.1480x; 1.5739x over previous
#include <cuda_runtime.h>
#include <cuda_fp16.h>
#include <cuda_bf16.h>
#include <cstdint>

#define DM     2048
#define NHEADS 16
#define DH     128
#define BATCH  2
#define SEQ    2048
#define MTOT   (BATCH*SEQ)   // 4096

// Scratch (allocation-free)
__device__ float         g_q  [(size_t)MTOT * DM];
__device__ float         g_k  [(size_t)MTOT * DM];
__device__ float         g_v  [(size_t)MTOT * DM];
__device__ __half        g_xh [(size_t)MTOT * DM];
__device__ __half        g_wh [(size_t)3 * DM * DM];
__device__ __nv_bfloat16 g_woh[(size_t)DM * DM];
__device__ __nv_bfloat16 g_wol[(size_t)DM * DM];
__device__ __nv_bfloat16 g_ath[(size_t)MTOT * DM];
__device__ __nv_bfloat16 g_atl[(size_t)MTOT * DM];

// ===========================================================================
// Helpers (sm_80-class PTX only — no tcgen05 on this harness's ptxas target)
// ===========================================================================
__device__ __forceinline__ uint32_t smem_u32(const void* p) {
    uint32_t a;
    asm("{ .reg .u64 t; cvta.to.shared.u64 t, %1; cvt.u32.u64 %0, t; }"
        : "=r"(a) : "l"(p));
    return a;
}
__device__ __forceinline__ uint32_t lds32(uint32_t a) {
    uint32_t v;
    asm volatile("ld.shared.b32 %0, [%1];" : "=r"(v) : "r"(a));
    return v;
}
__device__ __forceinline__ void sts64(uint32_t addr, uint32_t a, uint32_t b) {
    asm volatile("st.shared.v2.b32 [%0], {%1,%2};" :: "r"(addr), "r"(a), "r"(b) : "memory");
}
__device__ __forceinline__ uint32_t pack_bf16(float e0, float e1) {
    uint32_t r;
    asm("cvt.rn.bf16x2.f32 %0, %1, %2;" : "=r"(r) : "f"(e1), "f"(e0));
    return r;
}
__device__ __forceinline__ float ex2f(float x) {
    float y; asm("ex2.approx.f32 %0, %1;" : "=f"(y) : "f"(x)); return y;
}
__device__ __forceinline__ void ldsm4(uint32_t a, uint32_t& r0, uint32_t& r1,
                                      uint32_t& r2, uint32_t& r3) {
    asm volatile("ldmatrix.sync.aligned.m8n8.x4.shared.b16 {%0,%1,%2,%3}, [%4];"
        : "=r"(r0), "=r"(r1), "=r"(r2), "=r"(r3) : "r"(a));
}
__device__ __forceinline__ void ldsm4t(uint32_t addr, uint32_t& r0, uint32_t& r1,
                                       uint32_t& r2, uint32_t& r3) {
    asm volatile("ldmatrix.sync.aligned.m8n8.x4.trans.shared.b16 {%0,%1,%2,%3}, [%4];"
        : "=r"(r0), "=r"(r1), "=r"(r2), "=r"(r3) : "r"(addr));
}
__device__ __forceinline__ void cvt_split(float4 v, uint32_t& h01, uint32_t& h23,
                                          uint32_t& l01, uint32_t& l23) {
    asm("cvt.rn.bf16x2.f32 %0, %1, %2;" : "=r"(h01) : "f"(v.y), "f"(v.x));
    asm("cvt.rn.bf16x2.f32 %0, %1, %2;" : "=r"(h23) : "f"(v.w), "f"(v.z));
    float f0 = __uint_as_float(h01 << 16);
    float f1 = __uint_as_float(h01 & 0xffff0000u);
    float f2 = __uint_as_float(h23 << 16);
    float f3 = __uint_as_float(h23 & 0xffff0000u);
    asm("cvt.rn.bf16x2.f32 %0, %1, %2;" : "=r"(l01) : "f"(v.y - f1), "f"(v.x - f0));
    asm("cvt.rn.bf16x2.f32 %0, %1, %2;" : "=r"(l23) : "f"(v.w - f3), "f"(v.z - f2));
}
__device__ __forceinline__ void mma_bf16(float* d,
    uint32_t a0, uint32_t a1, uint32_t a2, uint32_t a3, uint32_t b0, uint32_t b1)
{
    asm volatile(
        "mma.sync.aligned.m16n8k16.row.col.f32.bf16.bf16.f32 "
        "{%0,%1,%2,%3}, {%4,%5,%6,%7}, {%8,%9}, {%0,%1,%2,%3};"
        : "+f"(d[0]), "+f"(d[1]), "+f"(d[2]), "+f"(d[3])
        : "r"(a0), "r"(a1), "r"(a2), "r"(a3), "r"(b0), "r"(b1));
}
__device__ __forceinline__ void mma_f16(float* d,
    uint32_t a0, uint32_t a1, uint32_t a2, uint32_t a3, uint32_t b0, uint32_t b1)
{
    asm volatile(
        "mma.sync.aligned.m16n8k16.row.col.f32.f16.f16.f32 "
        "{%0,%1,%2,%3}, {%4,%5,%6,%7}, {%8,%9}, {%0,%1,%2,%3};"
        : "+f"(d[0]), "+f"(d[1]), "+f"(d[2]), "+f"(d[3])
        : "r"(a0), "r"(a1), "r"(a2), "r"(a3), "r"(b0), "r"(b1));
}
#define CP_ASYNC16(sa, g) \
    asm volatile("cp.async.cg.shared.global [%0], [%1], 16;" :: "r"(sa), "l"(g) : "memory")
#define CP_COMMIT() asm volatile("cp.async.commit_group;" ::: "memory")
#define CP_WAIT(n)  asm volatile("cp.async.wait_group %0;" :: "n"(n) : "memory")

// ===========================================================================
// Conversion kernels (exact grids, no bounds checks)
// ===========================================================================
__global__ void conv_h_kernel(const float* __restrict__ s, __half* __restrict__ d) {
    int i = blockIdx.x * 256 + threadIdx.x;
    float4 v = ((const float4*)s)[i];
    ((__half2*)d)[2*i]   = __floats2half2_rn(v.x, v.y);
    ((__half2*)d)[2*i+1] = __floats2half2_rn(v.z, v.w);
}
__global__ void conv_split_kernel(const float* __restrict__ s,
                                  __nv_bfloat16* __restrict__ hi,
                                  __nv_bfloat16* __restrict__ lo) {
    int i = blockIdx.x * 256 + threadIdx.x;
    float4 v = ((const float4*)s)[i];
    uint32_t h01, h23, l01, l23;
    cvt_split(v, h01, h23, l01, l23);
    ((uint2*)hi)[i] = make_uint2(h01, h23);
    ((uint2*)lo)[i] = make_uint2(l01, l23);
}

// ===========================================================================
// QKV GEMM, fp16 single-MMA. Y = X @ W^T + b.  128x128 tile, BK=64, 3-stage
// cp.async pipeline, ldmatrix fragments. Smem rows padded to 144B (no-XOR
// conflict-free: 36 words/row -> 8 rows hit 32 distinct banks).
// ===========================================================================
#define QK_BOFF  18432                // 128*144
#define QK_STAGE 36864                // A + B tiles
#define QK_SMEM  (3*QK_STAGE)         // 110592 -> 2 CTAs/SM

__global__ __launch_bounds__(256, 2) void gemm_h_qkv(
    const float* __restrict__ bq, const float* __restrict__ bk,
    const float* __restrict__ bv,
    float* __restrict__ Yq, float* __restrict__ Yk, float* __restrict__ Yv)
{
    extern __shared__ char smem[];
    const uint32_t sb = smem_u32(smem);
    const int tid = threadIdx.x, wid = tid >> 5, lid = tid & 31;
    const int wm = wid >> 2, wn = wid & 3;
    const int m0 = blockIdx.y * 128, n0 = blockIdx.x * 128;
    const int z  = blockIdx.z;
    const __half* Ag0 = g_xh + (size_t)m0 * DM;
    const __half* Bg0 = g_wh + (size_t)z * DM * DM + (size_t)n0 * DM;
    const float* bias = (z == 0) ? bq : (z == 1) ? bk : bv;
    float* Y = (z == 0) ? Yq : (z == 1) ? Yk : Yv;

    float acc[4][4][4];
#pragma unroll
    for (int mi = 0; mi < 4; mi++)
#pragma unroll
        for (int ni = 0; ni < 4; ni++)
#pragma unroll
            for (int d = 0; d < 4; d++) acc[mi][ni][d] = 0.f;

    const int tr = tid >> 3;     // 0..31
    const int tc = tid & 7;      // 16B chunk within 128B row

    auto issue = [&](int s, int kc) {
        const uint32_t st = sb + s * QK_STAGE;
        const __half* Ag = Ag0 + kc * 64;
        const __half* Bg = Bg0 + kc * 64;
#pragma unroll
        for (int i = 0; i < 8; i++) {
            const int r = tr + (i & 3) * 32;
            const uint32_t sa = st + (i >> 2) * QK_BOFF + r * 144 + tc * 16;
            const __half* g = ((i >> 2) ? Bg : Ag) + (size_t)r * DM + tc * 8;
            CP_ASYNC16(sa, g);
        }
    };

    issue(0, 0); CP_COMMIT();
    issue(1, 1); CP_COMMIT();

    const uint32_t arow = wm*64 + (lid & 7) + ((lid >> 3) & 1) * 8;
    const uint32_t ach  = lid >> 4;
    const uint32_t nrow = wn*32 + (lid & 7) + ((lid >> 4) & 1) * 8;
    const uint32_t nch  = (lid >> 3) & 1;

    for (int kc = 0; kc < 32; kc++) {
        const int s = kc % 3;
        CP_WAIT(1);
        __syncthreads();
        const uint32_t st = sb + s * QK_STAGE;
#pragma unroll
        for (int kk = 0; kk < 4; kk++) {
            uint32_t a[4][4], bb[2][4];
#pragma unroll
            for (int mi = 0; mi < 4; mi++)
                ldsm4(st + (arow + mi*16) * 144 + (kk*2 + ach) * 16,
                      a[mi][0], a[mi][1], a[mi][2], a[mi][3]);
#pragma unroll
            for (int nj = 0; nj < 2; nj++)
                ldsm4(st + QK_BOFF + (nrow + nj*16) * 144 + (kk*2 + nch) * 16,
                      bb[nj][0], bb[nj][1], bb[nj][2], bb[nj][3]);
#pragma unroll
            for (int mi = 0; mi < 4; mi++)
#pragma unroll
                for (int ni = 0; ni < 4; ni++)
                    mma_f16(acc[mi][ni], a[mi][0], a[mi][1], a[mi][2], a[mi][3],
                            bb[ni >> 1][(ni & 1)*2], bb[ni >> 1][(ni & 1)*2 + 1]);
        }
        if (kc + 2 < 32) issue((kc + 2) % 3, kc + 2);
        CP_COMMIT();
    }
    CP_WAIT(0);

#pragma unroll
    for (int mi = 0; mi < 4; mi++) {
        const int row = m0 + wm*64 + mi*16 + (lid >> 2);
#pragma unroll
        for (int ni = 0; ni < 4; ni++) {
            const int col = n0 + wn*32 + ni*8 + 2*(lid & 3);
            float2 bbv = *(const float2*)(bias + col);
            *(float2*)(Y + (size_t)row * DM + col) =
                make_float2(acc[mi][ni][0] + bbv.x, acc[mi][ni][1] + bbv.y);
            *(float2*)(Y + (size_t)(row + 8) * DM + col) =
                make_float2(acc[mi][ni][2] + bbv.x, acc[mi][ni][3] + bbv.y);
        }
    }
}

// ===========================================================================
// O-proj GEMM, split-bf16 3-term (accuracy hedge). A = attention out (hi/lo
// written by flash), B = Wo hi/lo. BK=32, 5-stage cp.async, 80B padded rows.
// ===========================================================================
#define O_TILE  10240                 // 128*80
#define O_STAGE (4*O_TILE)            // Ah, Al, Bh, Bl
#define O_NS    5
#define O_SMEM  (O_NS*O_STAGE)        // 204800

__global__ __launch_bounds__(256) void gemm_o_kernel(
    const float* __restrict__ bias, float* __restrict__ Y)
{
    extern __shared__ char smem[];
    const uint32_t sb = smem_u32(smem);
    const int tid = threadIdx.x, wid = tid >> 5, lid = tid & 31;
    const int wm = wid >> 2, wn = wid & 3;
    const int m0 = blockIdx.y * 128, n0 = blockIdx.x * 128;

    float acc[4][4][4];
#pragma unroll
    for (int mi = 0; mi < 4; mi++)
#pragma unroll
        for (int ni = 0; ni < 4; ni++)
#pragma unroll
            for (int d = 0; d < 4; d++) acc[mi][ni][d] = 0.f;

    const int tr = tid >> 2;     // 0..63
    const int tc = tid & 3;      // 16B chunk within 64B row

    auto issue = [&](int s, int kc) {
        const uint32_t st = sb + s * O_STAGE;
#pragma unroll
        for (int i = 0; i < 8; i++) {
            const int t = i >> 1;
            const int r = tr + (i & 1) * 64;
            const uint32_t sa = st + t * O_TILE + r * 80 + tc * 16;
            const __nv_bfloat16* g =
                (t == 0 ? g_ath + (size_t)(m0 + r) * DM :
                 t == 1 ? g_atl + (size_t)(m0 + r) * DM :
                 t == 2 ? g_woh + (size_t)(n0 + r) * DM :
                          g_wol + (size_t)(n0 + r) * DM) + kc*32 + tc*8;
            CP_ASYNC16(sa, g);
        }
    };

    issue(0, 0); CP_COMMIT();
    issue(1, 1); CP_COMMIT();
    issue(2, 2); CP_COMMIT();
    issue(3, 3); CP_COMMIT();

    const uint32_t arow = wm*64 + (lid & 7) + ((lid >> 3) & 1) * 8;
    const uint32_t ach  = lid >> 4;
    const uint32_t nrow = wn*32 + (lid & 7) + ((lid >> 4) & 1) * 8;
    const uint32_t nch  = (lid >> 3) & 1;

    for (int kc = 0; kc < 64; kc++) {
        const int s = kc % O_NS;
        CP_WAIT(3);
        __syncthreads();
        const uint32_t st = sb + s * O_STAGE;
#pragma unroll
        for (int kk = 0; kk < 2; kk++) {
            uint32_t ah[4][4], al[4][4], bh[2][4], bl[2][4];
#pragma unroll
            for (int mi = 0; mi < 4; mi++) {
                uint32_t ad = st + (arow + mi*16) * 80 + (kk*2 + ach) * 16;
                ldsm4(ad,          ah[mi][0], ah[mi][1], ah[mi][2], ah[mi][3]);
                ldsm4(ad + O_TILE, al[mi][0], al[mi][1], al[mi][2], al[mi][3]);
            }
#pragma unroll
            for (int nj = 0; nj < 2; nj++) {
                uint32_t bd = st + 2*O_TILE + (nrow + nj*16) * 80 + (kk*2 + nch) * 16;
                ldsm4(bd,          bh[nj][0], bh[nj][1], bh[nj][2], bh[nj][3]);
                ldsm4(bd + O_TILE, bl[nj][0], bl[nj][1], bl[nj][2], bl[nj][3]);
            }
#pragma unroll
            for (int mi = 0; mi < 4; mi++)
#pragma unroll
                for (int ni = 0; ni < 4; ni++) {
                    uint32_t bh0 = bh[ni >> 1][(ni & 1)*2], bh1 = bh[ni >> 1][(ni & 1)*2 + 1];
                    uint32_t bl0 = bl[ni >> 1][(ni & 1)*2], bl1 = bl[ni >> 1][(ni & 1)*2 + 1];
                    mma_bf16(acc[mi][ni], ah[mi][0], ah[mi][1], ah[mi][2], ah[mi][3], bh0, bh1);
                    mma_bf16(acc[mi][ni], ah[mi][0], ah[mi][1], ah[mi][2], ah[mi][3], bl0, bl1);
                    mma_bf16(acc[mi][ni], al[mi][0], al[mi][1], al[mi][2], al[mi][3], bh0, bh1);
                }
        }
        if (kc + 4 < 64) issue((kc + 4) % O_NS, kc + 4);
        CP_COMMIT();
    }
    CP_WAIT(0);

#pragma unroll
    for (int mi = 0; mi < 4; mi++) {
        const int row = m0 + wm*64 + mi*16 + (lid >> 2);
#pragma unroll
        for (int ni = 0; ni < 4; ni++) {
            const int col = n0 + wn*32 + ni*8 + 2*(lid & 3);
            float2 bbv = *(const float2*)(bias + col);
            *(float2*)(Y + (size_t)row * DM + col) =
                make_float2(acc[mi][ni][0] + bbv.x, acc[mi][ni][1] + bbv.y);
            *(float2*)(Y + (size_t)(row + 8) * DM + col) =
                make_float2(acc[mi][ni][2] + bbv.x, acc[mi][ni][3] + bbv.y);
        }
    }
}

// ---------------------------------------------------------------------------
// RoPE in-place on Q and K
// ---------------------------------------------------------------------------
__global__ void rope_kernel(float* __restrict__ q, float* __restrict__ k,
                            const float* __restrict__ sinT,
                            const float* __restrict__ cosT)
{
    int bt  = blockIdx.x;
    int t   = bt & (SEQ - 1);
    int tid = threadIdx.x;
    int h = tid >> 6, d = tid & 63;
    float s = sinT[t*64 + d];
    float c = cosT[t*64 + d];
    size_t base = (size_t)bt * DM + h*DH + d;
    float q1 = q[base], q2 = q[base + 64];
    q[base]      = q1*c - q2*s;
    q[base + 64] = q1*s + q2*c;
    float k1 = k[base], k2 = k[base + 64];
    k[base]      = k1*c - k2*s;
    k[base + 64] = k1*s + k2*c;
}

// ===========================================================================
// Tensor-core flash attention (causal), split-bf16 3-term, exp2 softmax.
// Writes output directly as bf16 hi/lo (g_ath/g_atl) to feed O-proj.
// ===========================================================================
#define FROW    272
#define QH_OFF  0
#define QL_OFF  (128*FROW)
#define KH_OFF  (2*128*FROW)
#define KL_OFF  (KH_OFF + 64*FROW)
#define VH_OFF  (KL_OFF + 64*FROW)
#define VL_OFF  (VH_OFF + 64*FROW)
#define FA_SMEM (VL_OFF + 64*FROW)

__global__ __launch_bounds__(256) void flash_tc_kernel(
    const float* __restrict__ Q, const float* __restrict__ K,
    const float* __restrict__ V)
{
    extern __shared__ char smc[];
    const uint32_t sb = smem_u32(smc);
    const int tid = threadIdx.x;
    const int wid = tid >> 5;
    const int lid = tid & 31;
    const int r   = lid >> 2;
    const int cw  = lid & 3;
    const int i0  = blockIdx.x * 128;
    const int h   = blockIdx.y;
    const int b   = blockIdx.z;
    const float qscale = 0.08838834764831845f * 1.4426950408889634f;

    const float* Qg = Q + ((size_t)(b*SEQ + i0)) * DM + h*DH;
#pragma unroll
    for (int ii = 0; ii < 16; ii++) {
        int i  = tid + ii * 256;
        int rr = i >> 5, c4 = i & 31;
        float4 v = *(const float4*)(Qg + (size_t)rr * DM + c4 * 4);
        v.x *= qscale; v.y *= qscale; v.z *= qscale; v.w *= qscale;
        uint32_t h01, h23, l01, l23;
        cvt_split(v, h01, h23, l01, l23);
        uint32_t off = rr * FROW + c4 * 8;
        sts64(sb + QH_OFF + off, h01, h23);
        sts64(sb + QL_OFF + off, l01, l23);
    }

    float o[16][4];
#pragma unroll
    for (int t = 0; t < 16; t++)
#pragma unroll
        for (int d = 0; d < 4; d++) o[t][d] = 0.f;
    float m0 = -1e30f, m1 = -1e30f, l0 = 0.f, l1 = 0.f;

    const int row0 = i0 + 16*wid + r;
    const int row1 = row0 + 8;

    const int ntiles = (i0 >> 6) + 2;
    for (int jt = 0; jt < ntiles; jt++) {
        const int j0 = jt * 64;
        __syncthreads();
        const float* Kg = K + ((size_t)(b*SEQ + j0)) * DM + h*DH;
        const float* Vg = V + ((size_t)(b*SEQ + j0)) * DM + h*DH;
#pragma unroll
        for (int ii = 0; ii < 8; ii++) {
            int i  = tid + ii * 256;
            int rr = i >> 5, c4 = i & 31;
            uint32_t off = rr * FROW + c4 * 8;
            uint32_t h01, h23, l01, l23;
            float4 kv = *(const float4*)(Kg + (size_t)rr * DM + c4 * 4);
            cvt_split(kv, h01, h23, l01, l23);
            sts64(sb + KH_OFF + off, h01, h23);
            sts64(sb + KL_OFF + off, l01, l23);
            float4 vv = *(const float4*)(Vg + (size_t)rr * DM + c4 * 4);
            cvt_split(vv, h01, h23, l01, l23);
            sts64(sb + VH_OFF + off, h01, h23);
            sts64(sb + VL_OFF + off, l01, l23);
        }
        __syncthreads();

        if (j0 <= i0 + 16*wid + 15) {
            float s[8][4];
#pragma unroll
            for (int t = 0; t < 8; t++)
#pragma unroll
                for (int d = 0; d < 4; d++) s[t][d] = 0.f;

            const uint32_t qa = sb + QH_OFF + (16*wid + r) * FROW + cw * 4;
            const uint32_t kb = sb + KH_OFF + r * FROW + cw * 4;
#pragma unroll
            for (int kk = 0; kk < 8; kk++) {
                const uint32_t ko = kk * 32;
                uint32_t ah0 = lds32(qa + ko);
                uint32_t ah1 = lds32(qa + ko + 8*FROW);
                uint32_t ah2 = lds32(qa + ko + 16);
                uint32_t ah3 = lds32(qa + ko + 8*FROW + 16);
                uint32_t al0 = lds32(qa + ko + (QL_OFF - QH_OFF));
                uint32_t al1 = lds32(qa + ko + (QL_OFF - QH_OFF) + 8*FROW);
                uint32_t al2 = lds32(qa + ko + (QL_OFF - QH_OFF) + 16);
                uint32_t al3 = lds32(qa + ko + (QL_OFF - QH_OFF) + 8*FROW + 16);
#pragma unroll
                for (int t = 0; t < 8; t++) {
                    uint32_t kbt = kb + t * 8 * FROW + ko;
                    uint32_t bh0 = lds32(kbt);
                    uint32_t bh1 = lds32(kbt + 16);
                    uint32_t bl0 = lds32(kbt + (KL_OFF - KH_OFF));
                    uint32_t bl1 = lds32(kbt + (KL_OFF - KH_OFF) + 16);
                    mma_bf16(s[t], ah0, ah1, ah2, ah3, bh0, bh1);
                    mma_bf16(s[t], ah0, ah1, ah2, ah3, bl0, bl1);
                    mma_bf16(s[t], al0, al1, al2, al3, bh0, bh1);
                }
            }

            if (j0 + 63 > i0 + 16*wid) {
#pragma unroll
                for (int t = 0; t < 8; t++) {
                    int c0 = j0 + t*8 + 2*cw;
                    if (c0     > row0) s[t][0] = -1e30f;
                    if (c0 + 1 > row0) s[t][1] = -1e30f;
                    if (c0     > row1) s[t][2] = -1e30f;
                    if (c0 + 1 > row1) s[t][3] = -1e30f;
                }
            }

            float mx0 = -1e30f, mx1 = -1e30f;
#pragma unroll
            for (int t = 0; t < 8; t++) {
                mx0 = fmaxf(mx0, fmaxf(s[t][0], s[t][1]));
                mx1 = fmaxf(mx1, fmaxf(s[t][2], s[t][3]));
            }
            mx0 = fmaxf(mx0, __shfl_xor_sync(0xffffffffu, mx0, 1));
            mx0 = fmaxf(mx0, __shfl_xor_sync(0xffffffffu, mx0, 2));
            mx1 = fmaxf(mx1, __shfl_xor_sync(0xffffffffu, mx1, 1));
            mx1 = fmaxf(mx1, __shfl_xor_sync(0xffffffffu, mx1, 2));
            float mn0 = fmaxf(m0, mx0), mn1 = fmaxf(m1, mx1);
            float al_0 = ex2f(m0 - mn0), al_1 = ex2f(m1 - mn1);
            m0 = mn0; m1 = mn1;
            float rs0 = 0.f, rs1 = 0.f;
#pragma unroll
            for (int t = 0; t < 8; t++) {
                s[t][0] = ex2f(s[t][0] - mn0);
                s[t][1] = ex2f(s[t][1] - mn0);
                s[t][2] = ex2f(s[t][2] - mn1);
                s[t][3] = ex2f(s[t][3] - mn1);
                rs0 += s[t][0] + s[t][1];
                rs1 += s[t][2] + s[t][3];
            }
            rs0 += __shfl_xor_sync(0xffffffffu, rs0, 1);
            rs0 += __shfl_xor_sync(0xffffffffu, rs0, 2);
            rs1 += __shfl_xor_sync(0xffffffffu, rs1, 1);
            rs1 += __shfl_xor_sync(0xffffffffu, rs1, 2);
            l0 = l0 * al_0 + rs0;
            l1 = l1 * al_1 + rs1;
#pragma unroll
            for (int t = 0; t < 16; t++) {
                o[t][0] *= al_0; o[t][1] *= al_0;
                o[t][2] *= al_1; o[t][3] *= al_1;
            }

            uint32_t aph[4][4], apl[4][4];
#pragma unroll
            for (int kk = 0; kk < 4; kk++) {
#pragma unroll
                for (int half = 0; half < 2; half++) {
                    int t = 2*kk + half;
                    uint32_t hA = pack_bf16(s[t][0], s[t][1]);
                    uint32_t hB = pack_bf16(s[t][2], s[t][3]);
                    float h0 = __uint_as_float(hA << 16);
                    float h1 = __uint_as_float(hA & 0xffff0000u);
                    float h2 = __uint_as_float(hB << 16);
                    float h3 = __uint_as_float(hB & 0xffff0000u);
                    aph[kk][2*half]   = hA;
                    aph[kk][2*half+1] = hB;
                    apl[kk][2*half]   = pack_bf16(s[t][0]-h0, s[t][1]-h1);
                    apl[kk][2*half+1] = pack_bf16(s[t][2]-h2, s[t][3]-h3);
                }
            }

            const uint32_t vrow = sb + VH_OFF + (lid & 15) * FROW + ((lid >> 4) << 4);
#pragma unroll
            for (int kk = 0; kk < 4; kk++) {
                const uint32_t vk = vrow + kk * 16 * FROW;
#pragma unroll
                for (int tp = 0; tp < 8; tp++) {
                    uint32_t vh0, vh1, vh2, vh3, vl0, vl1, vl2, vl3;
                    ldsm4t(vk + tp * 32, vh0, vh1, vh2, vh3);
                    ldsm4t(vk + tp * 32 + (VL_OFF - VH_OFF), vl0, vl1, vl2, vl3);
                    mma_bf16(o[2*tp],   aph[kk][0], aph[kk][1], aph[kk][2], aph[kk][3], vh0, vh1);
                    mma_bf16(o[2*tp],   aph[kk][0], aph[kk][1], aph[kk][2], aph[kk][3], vl0, vl1);
                    mma_bf16(o[2*tp],   apl[kk][0], apl[kk][1], apl[kk][2], apl[kk][3], vh0, vh1);
                    mma_bf16(o[2*tp+1], aph[kk][0], aph[kk][1], aph[kk][2], aph[kk][3], vh2, vh3);
                    mma_bf16(o[2*tp+1], aph[kk][0], aph[kk][1], aph[kk][2], aph[kk][3], vl2, vl3);
                    mma_bf16(o[2*tp+1], apl[kk][0], apl[kk][1], apl[kk][2], apl[kk][3], vh2, vh3);
                }
            }
        }
    }

    // epilogue: normalize, split to bf16 hi/lo, store to g_ath/g_atl
    const float inv0 = 1.0f / l0;
    const float inv1 = 1.0f / l1;
    const size_t base0 = ((size_t)(b*SEQ + row0)) * DM + h*DH;
#pragma unroll
    for (int t = 0; t < 16; t++) {
        const int col = t*8 + 2*cw;
        float a0 = o[t][0]*inv0, a1 = o[t][1]*inv0;
        float c0 = o[t][2]*inv1, c1 = o[t][3]*inv1;
        uint32_t ph = pack_bf16(a0, a1);
        uint32_t pl = pack_bf16(a0 - __uint_as_float(ph << 16),
                                a1 - __uint_as_float(ph & 0xffff0000u));
        *(uint32_t*)(g_ath + base0 + col) = ph;
        *(uint32_t*)(g_atl + base0 + col) = pl;
        uint32_t qh = pack_bf16(c0, c1);
        uint32_t ql = pack_bf16(c0 - __uint_as_float(qh << 16),
                                c1 - __uint_as_float(qh & 0xffff0000u));
        *(uint32_t*)(g_ath + base0 + 8*DM + col) = qh;
        *(uint32_t*)(g_atl + base0 + 8*DM + col) = ql;
    }
}

// ---------------------------------------------------------------------------
extern "C" void kernel_launch(void* const* d_in, const int* in_sizes, int n_in,
                              void* d_out, int out_size)
{
    (void)in_sizes; (void)n_in; (void)out_size;
    const float* x    = (const float*)d_in[0];
    const float* Wq   = (const float*)d_in[1];
    const float* bq   = (const float*)d_in[2];
    const float* Wk   = (const float*)d_in[3];
    const float* bk   = (const float*)d_in[4];
    const float* Wv   = (const float*)d_in[5];
    const float* bv   = (const float*)d_in[6];
    const float* Wo   = (const float*)d_in[7];
    const float* bo   = (const float*)d_in[8];
    const float* sinT = (const float*)d_in[9];
    const float* cosT = (const float*)d_in[10];
    float* out = (float*)d_out;

    void *pq, *pk, *pv, *pxh, *pwh, *pwoh, *pwol;
    cudaGetSymbolAddress(&pq,  g_q);
    cudaGetSymbolAddress(&pk,  g_k);
    cudaGetSymbolAddress(&pv,  g_v);
    cudaGetSymbolAddress(&pxh, g_xh);
    cudaGetSymbolAddress(&pwh, g_wh);
    cudaGetSymbolAddress(&pwoh, g_woh);
    cudaGetSymbolAddress(&pwol, g_wol);
    float* q = (float*)pq;
    float* k = (float*)pk;
    float* v = (float*)pv;
    __half* xh = (__half*)pxh;
    __half* wh = (__half*)pwh;
    __nv_bfloat16* woh = (__nv_bfloat16*)pwoh;
    __nv_bfloat16* wol = (__nv_bfloat16*)pwol;

    cudaFuncSetAttribute(gemm_h_qkv,
                         cudaFuncAttributeMaxDynamicSharedMemorySize, QK_SMEM);
    cudaFuncSetAttribute(gemm_o_kernel,
                         cudaFuncAttributeMaxDynamicSharedMemorySize, O_SMEM);
    cudaFuncSetAttribute(flash_tc_kernel,
                         cudaFuncAttributeMaxDynamicSharedMemorySize, FA_SMEM);

    // Conversions (exact grids)
    conv_h_kernel<<<(MTOT*DM)/1024, 256>>>(x, xh);
    conv_h_kernel<<<(DM*DM)/1024, 256>>>(Wq, wh);
    conv_h_kernel<<<(DM*DM)/1024, 256>>>(Wk, wh + (size_t)DM*DM);
    conv_h_kernel<<<(DM*DM)/1024, 256>>>(Wv, wh + (size_t)2*DM*DM);
    conv_split_kernel<<<(DM*DM)/1024, 256>>>(Wo, woh, wol);

    gemm_h_qkv<<<dim3(DM/128, MTOT/128, 3), 256, QK_SMEM>>>(bq, bk, bv, q, k, v);

    rope_kernel<<<MTOT, 1024>>>(q, k, sinT, cosT);

    flash_tc_kernel<<<dim3(SEQ/128, NHEADS, BATCH), 256, FA_SMEM>>>(q, k, v);

    gemm_o_kernel<<<dim3(DM/128, MTOT/128), 256, O_SMEM>>>(bo, out);
}